// round 14
// baseline (speedup 1.0000x reference)
#include <cuda_runtime.h>
#include <cuda_bf16.h>
#include <math.h>

#define BATCH 128
#define SEQT  512
#define TSTEPS 518   // 512 + 6 pipeline offsets
#define NBLK 148

// ---- device-global scratch (allocation-free rule) ----
__device__ float g_xk[(size_t)BATCH * SEQT * 2560];  // layer-1 input proj [T][4][640][B] fp32
// split-bf16 hidden state, k-pair packed: u32 = bf16(k even) | bf16(k odd)<<16
// layout [par][kpair][B]; kpair offsets: l1 0, l2 320, l3 520, l4 648; total 776
__device__ unsigned int g_h2hi[2][776 * 128];
__device__ unsigned int g_h2lo[2][776 * 128];
__device__ float g_cbuf[1552 * 128];                 // fp32 cell state, j offsets 0/640/1040/1296
__device__ float g_xkbuf[2][3648 * 128];             // proj outputs fp32, offsets l2 0, l3 1600, l4 2624
__device__ unsigned int g_bar;

// ---- packed f32x2 helpers (used by the standalone gemm) ----
__device__ __forceinline__ unsigned long long pack2(float x, float y) {
    unsigned long long d;
    asm("mov.b64 %0, {%1, %2};" : "=l"(d) : "f"(x), "f"(y));
    return d;
}
__device__ __forceinline__ unsigned long long ffma2(unsigned long long a,
                                                    unsigned long long b,
                                                    unsigned long long c) {
    unsigned long long d;
    asm("fma.rn.f32x2 %0, %1, %2, %3;" : "=l"(d) : "l"(a), "l"(b), "l"(c));
    return d;
}
__device__ __forceinline__ void unpack2(unsigned long long v, float& lo, float& hi) {
    asm("mov.b64 {%0, %1}, %2;" : "=f"(lo), "=f"(hi) : "l"(v));
}
__device__ __forceinline__ float sigf(float v) { return 1.f / (1.f + expf(-v)); }

__device__ __forceinline__ int kpbase(int l) {
    return (l == 1) ? 0 : (l == 2) ? 320 : (l == 3) ? 520 : 648;
}
__device__ __forceinline__ float* cbuf_ptr(int l) {
    const int off = (l == 1) ? 0 : (l == 2) ? 640 : (l == 3) ? 1040 : 1296;
    return g_cbuf + (size_t)off * 128;
}
__device__ __forceinline__ float* xkb_ptr(int par, int l) {
    const int off = (l == 2) ? 0 : (l == 3) ? 1600 : 2624;
    return g_xkbuf[par] + (size_t)off * 128;
}

// bf16 mma: D += A(16x16) * B(16x8), A row-major frag, B col-major frag, f32 acc
__device__ __forceinline__ void mma_bf16(float* d,
                                         unsigned a0, unsigned a1, unsigned a2, unsigned a3,
                                         unsigned b0, unsigned b1) {
    asm volatile("mma.sync.aligned.m16n8k16.row.col.f32.bf16.bf16.f32 "
                 "{%0,%1,%2,%3}, {%4,%5,%6,%7}, {%8,%9}, {%0,%1,%2,%3};"
                 : "+f"(d[0]), "+f"(d[1]), "+f"(d[2]), "+f"(d[3])
                 : "r"(a0), "r"(a1), "r"(a2), "r"(a3), "r"(b0), "r"(b1));
}

// ---- reset state before wavefront ----
__global__ void reset_all() {
    size_t i = (size_t)blockIdx.x * blockDim.x + threadIdx.x;
    const size_t N1 = (size_t)2 * 776 * 128;   // 198656
    if (i < N1) { (&g_h2hi[0][0])[i] = 0u; (&g_h2lo[0][0])[i] = 0u; }
    if (i < (size_t)1552 * 128) g_cbuf[i] = 0.f;
    if (i == 0) g_bar = 0u;
}

// ---- layer-1 input-projection GEMM: x[B][T][64] @ k1 -> g_xk [t][4][640][B] fp32 ----
__global__ void gemm_bias_kernel(const float* __restrict__ A, const float* __restrict__ W,
                                 const float* __restrict__ bias, float* __restrict__ C,
                                 int M, int N, int K) {
    __shared__ float As[16][64];
    __shared__ float Ws[16][64];
    const int H = N >> 2;
    int tid = threadIdx.x;
    int n0 = blockIdx.x * 64, m0 = blockIdx.y * 64;
    int tn = tid & 15, tm = tid >> 4;
    int ak = tid & 15, am = tid >> 4;
    int wn = tid & 63, wk = tid >> 6;

    unsigned long long acc01[4], acc23[4];
#pragma unroll
    for (int i = 0; i < 4; i++) { acc01[i] = pack2(0.f, 0.f); acc23[i] = acc01[i]; }

    size_t srow[4];
#pragma unroll
    for (int i = 0; i < 4; i++) {
        int m = m0 + am + i * 16;
        srow[i] = (size_t)(m % BATCH) * SEQT + (size_t)(m / BATCH);
    }

    for (int k0 = 0; k0 < K; k0 += 16) {
#pragma unroll
        for (int i = 0; i < 4; i++)
            As[ak][am + i * 16] = A[srow[i] * K + k0 + ak];
#pragma unroll
        for (int i = 0; i < 4; i++)
            Ws[wk + i * 4][wn] = W[(size_t)(k0 + wk + i * 4) * N + n0 + wn];
        __syncthreads();
#pragma unroll
        for (int k = 0; k < 16; k++) {
            float4 a4 = *(const float4*)&As[k][tm * 4];
            float4 w4 = *(const float4*)&Ws[k][tn * 4];
            unsigned long long a01 = pack2(a4.x, a4.y);
            unsigned long long a23 = pack2(a4.z, a4.w);
            float warr[4] = {w4.x, w4.y, w4.z, w4.w};
#pragma unroll
            for (int j4 = 0; j4 < 4; j4++) {
                unsigned long long wd = pack2(warr[j4], warr[j4]);
                acc01[j4] = ffma2(a01, wd, acc01[j4]);
                acc23[j4] = ffma2(a23, wd, acc23[j4]);
            }
        }
        __syncthreads();
    }
    int t = m0 >> 7;
    int bb = (m0 & 127) + tm * 4;
#pragma unroll
    for (int j4 = 0; j4 < 4; j4++) {
        int n = n0 + tn * 4 + j4;
        int g = n / H;
        int jj = n - g * H;
        float bn = bias[n];
        float v0, v1, v2, v3;
        unpack2(acc01[j4], v0, v1);
        unpack2(acc23[j4], v2, v3);
        *(float4*)&C[((size_t)(t * 4 + g) * H + jj) * 128 + bb] =
            make_float4(v0 + bn, v1 + bn, v2 + bn, v3 + bn);
    }
}

// ---- grid barrier (148 blocks, 1/SM guaranteed by smem) ----
__device__ __forceinline__ void grid_sync(unsigned int target) {
    __threadfence();            // all threads: publish h/c/xk stores gpu-wide
    __syncthreads();
    if (threadIdx.x == 0) {
        atomicAdd(&g_bar, 1u);
        unsigned int v;
        do {
            asm volatile("ld.acquire.gpu.u32 %0, [%1];" : "=r"(v) : "l"(&g_bar));
        } while (v < target);
    }
    __syncthreads();
}

// ---- wavefront persistent loop with split-bf16 MMA ----
// 256 threads = 8 warps; warp w owns batch rows 16w..16w+15 (M=128).
// Block owns ntiles n8-tiles of the output (n = local_j*4 + gate).
// A (h) staged per k16 chunk as k-pair u32 [8][136] hi/lo, double buffered.
// Weights resident in smem as [n][KPW] k-pair u32 hi/lo.
// TERM-MAJOR inner order: all hi*hi MMAs across tiles, then hi*lo, then lo*hi —
// RAW distance per accumulator = ntiles MMAs instead of 1 (hides HMMA latency).
template<int MAXNT>
__device__ __forceinline__ void persist_loop(
    int isrec, int layer, int Hin, int Hout, int ntiles, int jstart, int toff,
    const float* __restrict__ bias,
    const unsigned int* __restrict__ wsmHi, const unsigned int* __restrict__ wsmLo,
    unsigned int* __restrict__ bufA, float* __restrict__ zbuf, int KPW,
    const float* __restrict__ xk1)
{
    const int tid = threadIdx.x;
    const int lane = tid & 31, w = tid >> 5;
    const int r = lane >> 2, cc = lane & 3;
    const unsigned int nb = gridDim.x;
    const int NKC = Hin >> 4;
    const int srcl = isrec ? layer : layer - 1;
    const int srcKp = kpbase(srcl);
    const int dstKp = kpbase(layer);
    float* cst = cbuf_ptr(layer);
    const int klq = tid >> 5;            // staging row 0..7
    const int bq = (tid & 31) * 4;       // staging col

    for (int s = 0; s < TSTEPS; s++) {
        int t = s - toff;
        if (t >= 0 && t < SEQT) {
            int par = t & 1;
            int spar = isrec ? (par ^ 1) : par;
            const unsigned int* hsHi = g_h2hi[spar] + (size_t)srcKp * 128;
            const unsigned int* hsLo = g_h2lo[spar] + (size_t)srcKp * 128;

            float acc[MAXNT][4];
#pragma unroll
            for (int nt = 0; nt < MAXNT; nt++) {
                acc[nt][0] = 0.f; acc[nt][1] = 0.f; acc[nt][2] = 0.f; acc[nt][3] = 0.f;
            }

            // stage chunk 0
            uint4 pfh = *(const uint4*)(hsHi + tid * 4);
            uint4 pfl = *(const uint4*)(hsLo + tid * 4);
            *(uint4*)(bufA + klq * 136 + bq) = pfh;
            *(uint4*)(bufA + 1088 + klq * 136 + bq) = pfl;
            __syncthreads();
            if (NKC > 1) {
                pfh = *(const uint4*)(hsHi + 1024 + tid * 4);
                pfl = *(const uint4*)(hsLo + 1024 + tid * 4);
            }

            for (int c = 0; c < NKC; c++) {
                const unsigned int* bh = bufA + (c & 1) * 2176;
                const unsigned int* bl = bh + 1088;
                // A fragments (k16 x 16 rows of this warp), hi and lo
                unsigned ah0 = bh[cc * 136 + 16 * w + r];
                unsigned ah1 = bh[cc * 136 + 16 * w + r + 8];
                unsigned ah2 = bh[(cc + 4) * 136 + 16 * w + r];
                unsigned ah3 = bh[(cc + 4) * 136 + 16 * w + r + 8];
                unsigned al0 = bl[cc * 136 + 16 * w + r];
                unsigned al1 = bl[cc * 136 + 16 * w + r + 8];
                unsigned al2 = bl[(cc + 4) * 136 + 16 * w + r];
                unsigned al3 = bl[(cc + 4) * 136 + 16 * w + r + 8];
                int kp0 = c * 8;
                // term 0: hi*hi across all tiles
#pragma unroll
                for (int nt = 0; nt < MAXNT; nt++) {
                    if (nt < ntiles) {
                        int n = nt * 8 + r;
                        mma_bf16(acc[nt], ah0, ah1, ah2, ah3,
                                 wsmHi[n * KPW + kp0 + cc], wsmHi[n * KPW + kp0 + cc + 4]);
                    }
                }
                // term 1: hi*lo across all tiles
#pragma unroll
                for (int nt = 0; nt < MAXNT; nt++) {
                    if (nt < ntiles) {
                        int n = nt * 8 + r;
                        mma_bf16(acc[nt], ah0, ah1, ah2, ah3,
                                 wsmLo[n * KPW + kp0 + cc], wsmLo[n * KPW + kp0 + cc + 4]);
                    }
                }
                // term 2: lo*hi across all tiles
#pragma unroll
                for (int nt = 0; nt < MAXNT; nt++) {
                    if (nt < ntiles) {
                        int n = nt * 8 + r;
                        mma_bf16(acc[nt], al0, al1, al2, al3,
                                 wsmHi[n * KPW + kp0 + cc], wsmHi[n * KPW + kp0 + cc + 4]);
                    }
                }
                if (c + 1 < NKC) {
                    unsigned int* dh = bufA + ((c + 1) & 1) * 2176;
                    *(uint4*)(dh + klq * 136 + bq) = pfh;
                    *(uint4*)(dh + 1088 + klq * 136 + bq) = pfl;
                    __syncthreads();
                    if (c + 2 < NKC) {
                        pfh = *(const uint4*)(hsHi + (size_t)(c + 2) * 1024 + tid * 4);
                        pfl = *(const uint4*)(hsLo + (size_t)(c + 2) * 1024 + tid * 4);
                    }
                }
            }

            // D fragments -> zbuf[n][b] (pitch 132)
#pragma unroll
            for (int nt = 0; nt < MAXNT; nt++) {
                if (nt < ntiles) {
                    int nb0 = nt * 8 + 2 * cc;
                    int br = 16 * w + r;
                    zbuf[nb0 * 132 + br] = acc[nt][0];
                    zbuf[(nb0 + 1) * 132 + br] = acc[nt][1];
                    zbuf[nb0 * 132 + br + 8] = acc[nt][2];
                    zbuf[(nb0 + 1) * 132 + br + 8] = acc[nt][3];
                }
            }
            __syncthreads();

            if (isrec) {
                const float* xsrc = (layer == 1) ? (xk1 + (size_t)t * 2560 * 128)
                                                 : xkb_ptr(par, layer);
                __nv_bfloat16* hh = (__nv_bfloat16*)(g_h2hi[par] + (size_t)dstKp * 128);
                __nv_bfloat16* hl = (__nv_bfloat16*)(g_h2lo[par] + (size_t)dstKp * 128);
#pragma unroll
                for (int e = 0; e < MAXNT; e++) {
                    if (e < ntiles) {
                        int idx = e * 256 + tid;
                        int jl = idx >> 7, b = idx & 127;
                        int jg = jstart + jl;
                        float zi = zbuf[(jl * 4 + 0) * 132 + b] + xsrc[(size_t)(0 * Hout + jg) * 128 + b];
                        float zf = zbuf[(jl * 4 + 1) * 132 + b] + xsrc[(size_t)(1 * Hout + jg) * 128 + b];
                        float zg = zbuf[(jl * 4 + 2) * 132 + b] + xsrc[(size_t)(2 * Hout + jg) * 128 + b];
                        float zo = zbuf[(jl * 4 + 3) * 132 + b] + xsrc[(size_t)(3 * Hout + jg) * 128 + b];
                        float ig = sigf(zi), fg = sigf(zf);
                        float gg = tanhf(zg), og = sigf(zo);
                        size_t ci = (size_t)jg * 128 + b;
                        float cn = fg * cst[ci] + ig * gg;
                        float h = og * tanhf(cn);
                        cst[ci] = cn;
                        __nv_bfloat16 hhi = __float2bfloat16(h);
                        __nv_bfloat16 hlo = __float2bfloat16(h - __bfloat162float(hhi));
                        size_t widx = ((size_t)(jg >> 1) * 128 + b) * 2 + (jg & 1);
                        hh[widx] = hhi;
                        hl[widx] = hlo;
                    }
                }
            } else {
                float* dst = xkb_ptr(par, layer);
#pragma unroll
                for (int e = 0; e < MAXNT; e++) {
                    if (e < ntiles) {
                        int idx = e * 256 + tid;
                        int jl = idx >> 7, b = idx & 127;
                        int jg = jstart + jl;
#pragma unroll
                        for (int g = 0; g < 4; g++)
                            dst[(size_t)(g * Hout + jg) * 128 + b] =
                                zbuf[(jl * 4 + g) * 132 + b] + bias[g * Hout + jg];
                    }
                }
            }
        }
        grid_sync((unsigned int)(s + 1) * nb);
    }
}

__global__ void __launch_bounds__(256, 1)
fused_lstm(const float* __restrict__ R1, const float* __restrict__ K2,
           const float* __restrict__ B2, const float* __restrict__ R2,
           const float* __restrict__ K3, const float* __restrict__ B3,
           const float* __restrict__ R3, const float* __restrict__ K4,
           const float* __restrict__ B4, const float* __restrict__ R4,
           const float* __restrict__ xk1) {
    extern __shared__ unsigned int smem[];

    // roles: 0 L1rec, 1 L2proj, 2 L2rec, 3 L3proj, 4 L3rec, 5 L4proj, 6 L4rec
    const int r_nb[7]    = {54, 34, 21, 13, 9, 9, 8};
    const int r_rec[7]   = {1, 0, 1, 0, 1, 0, 1};
    const int r_layer[7] = {1, 2, 2, 3, 3, 4, 4};
    const int r_Hin[7]   = {640, 640, 400, 400, 256, 256, 256};
    const int r_Hout[7]  = {640, 400, 400, 256, 256, 256, 256};
    const int r_tiles[7] = {320, 200, 200, 128, 128, 128, 128};

    int bid = blockIdx.x;
    int role = 0, start = 0;
    {
        int s2 = 0;
        for (int rr = 0; rr < 7; rr++) {
            if (bid >= s2 && bid < s2 + r_nb[rr]) { role = rr; start = s2; }
            s2 += r_nb[rr];
        }
    }
    int ridx = bid - start;
    const int Hin = r_Hin[role], Hout = r_Hout[role];
    const int layer = r_layer[role], isrec = r_rec[role];
    const int T = r_tiles[role];
    const int q = T / r_nb[role], rm = T % r_nb[role];
    const int ntiles = q + (ridx < rm ? 1 : 0);
    const int tstart = ridx * q + (ridx < rm ? ridx : rm);
    const int jstart = tstart * 2;
    const int kpairs = Hin >> 1;
    const int KPW = (Hin == 640) ? 324 : (Hin == 400) ? 228 : 132;
    const int Nn = ntiles * 8;

    unsigned int* wsmHi = smem;
    unsigned int* wsmLo = smem + (size_t)Nn * KPW;
    unsigned int* bufA = wsmLo + (size_t)Nn * KPW;
    float* zbuf = (float*)(bufA + 4352);

    const float* Wsel = (role == 0) ? R1 : (role == 1) ? K2 : (role == 2) ? R2
                       : (role == 3) ? K3 : (role == 4) ? R3 : (role == 5) ? K4 : R4;
    const float* bias = (role == 1) ? B2 : (role == 3) ? B3 : (role == 5) ? B4 : (const float*)0;

    // preamble: load fp32 weights, convert to split-bf16 k-pair u32 layout [n][KPW]
    {
        int tid = threadIdx.x;
        int tot = Nn * kpairs;
        for (int e = tid; e < tot; e += 256) {
            int n = e / kpairs, kp = e - n * kpairs;
            int jl = n >> 2, g = n & 3;
            int gcol = g * Hout + jstart + jl;
            float w0 = Wsel[(size_t)(2 * kp) * (4 * Hout) + gcol];
            float w1 = Wsel[(size_t)(2 * kp + 1) * (4 * Hout) + gcol];
            __nv_bfloat16 h0 = __float2bfloat16(w0);
            __nv_bfloat16 l0 = __float2bfloat16(w0 - __bfloat162float(h0));
            __nv_bfloat16 h1 = __float2bfloat16(w1);
            __nv_bfloat16 l1 = __float2bfloat16(w1 - __bfloat162float(h1));
            wsmHi[n * KPW + kp] = (unsigned)__bfloat16_as_ushort(h0)
                                | ((unsigned)__bfloat16_as_ushort(h1) << 16);
            wsmLo[n * KPW + kp] = (unsigned)__bfloat16_as_ushort(l0)
                                | ((unsigned)__bfloat16_as_ushort(l1) << 16);
        }
    }
    __syncthreads();

    if (role <= 1)
        persist_loop<6>(isrec, layer, Hin, Hout, ntiles, jstart, role, bias,
                        wsmHi, wsmLo, bufA, zbuf, KPW, xk1);
    else if (role <= 3)
        persist_loop<10>(isrec, layer, Hin, Hout, ntiles, jstart, role, bias,
                         wsmHi, wsmLo, bufA, zbuf, KPW, xk1);
    else
        persist_loop<16>(isrec, layer, Hin, Hout, ntiles, jstart, role, bias,
                         wsmHi, wsmLo, bufA, zbuf, KPW, xk1);
}

// ---- dense head: 6 FC layers + softmax; h4 from split-bf16 (par 1) ----
__device__ __forceinline__ void dense_layer(const float* __restrict__ W,
                                            const float* __restrict__ bi,
                                            const float* in, float* out2,
                                            int din, int dout, bool relu) {
    for (int j = threadIdx.x; j < dout; j += blockDim.x) {
        float s = bi[j];
        for (int kk = 0; kk < din; kk++) s += in[kk] * W[(size_t)kk * dout + j];
        out2[j] = relu ? fmaxf(s, 0.f) : s;
    }
    __syncthreads();
}

__global__ void dense_head_kernel(const float* w1, const float* b1,
                                  const float* w2, const float* b2,
                                  const float* w3, const float* b3,
                                  const float* w4, const float* b4,
                                  const float* w5, const float* b5,
                                  const float* w6, const float* b6,
                                  float* __restrict__ out) {
    __shared__ float bufa[512], bufb[512];
    int b = blockIdx.x;
    const __nv_bfloat16* hh = (const __nv_bfloat16*)(g_h2hi[1] + (size_t)648 * 128);
    const __nv_bfloat16* hl = (const __nv_bfloat16*)(g_h2lo[1] + (size_t)648 * 128);
    for (int j = threadIdx.x; j < 256; j += blockDim.x) {
        size_t widx = ((size_t)(j >> 1) * 128 + b) * 2 + (j & 1);
        bufa[j] = __bfloat162float(hh[widx]) + __bfloat162float(hl[widx]);
    }
    __syncthreads();
    dense_layer(w1, b1, bufa, bufb, 256, 512, true);
    dense_layer(w2, b2, bufb, bufa, 512, 256, true);
    dense_layer(w3, b3, bufa, bufb, 256, 128, true);
    dense_layer(w4, b4, bufb, bufa, 128, 64, true);
    dense_layer(w5, b5, bufa, bufb, 64, 16, true);
    dense_layer(w6, b6, bufb, bufa, 16, 3, false);
    if (threadIdx.x == 0) {
        float m = fmaxf(bufa[0], fmaxf(bufa[1], bufa[2]));
        float e0 = expf(bufa[0] - m), e1 = expf(bufa[1] - m), e2 = expf(bufa[2] - m);
        float s = e0 + e1 + e2;
        out[b * 3 + 0] = e0 / s;
        out[b * 3 + 1] = e1 / s;
        out[b * 3 + 2] = e2 / s;
    }
}

extern "C" void kernel_launch(void* const* d_in, const int* in_sizes, int n_in,
                              void* d_out, int out_size) {
    const float* x  = (const float*)d_in[0];
    const float* k1 = (const float*)d_in[1];
    const float* r1 = (const float*)d_in[2];
    const float* b1 = (const float*)d_in[3];
    const float* k2 = (const float*)d_in[4];
    const float* r2 = (const float*)d_in[5];
    const float* b2 = (const float*)d_in[6];
    const float* k3 = (const float*)d_in[7];
    const float* r3 = (const float*)d_in[8];
    const float* b3 = (const float*)d_in[9];
    const float* k4 = (const float*)d_in[10];
    const float* r4 = (const float*)d_in[11];
    const float* b4 = (const float*)d_in[12];
    const float* WD[6];
    const float* BD[6];
    for (int i = 0; i < 6; i++) {
        WD[i] = (const float*)d_in[13 + 2 * i];
        BD[i] = (const float*)d_in[14 + 2 * i];
    }

    float* xk;
    cudaGetSymbolAddress((void**)&xk, g_xk);

    // max smem over roles: role6 = (2*128*132 + 4352)*4 + 128*132*4 = 220160 B
    const int SMEMB = 220160;
    cudaFuncSetAttribute(fused_lstm, cudaFuncAttributeMaxDynamicSharedMemorySize, SMEMB);

    const int M = BATCH * SEQT;

    // 1) layer-1 input projection GEMM (fp32)
    gemm_bias_kernel<<<dim3(2560 / 64, M / 64), 256>>>(x, k1, b1, xk, M, 2560, 64);
    // 2) zero h/c/barrier
    reset_all<<<776, 256>>>();
    // 3) fused 4-layer wavefront with split-bf16 tensor-core matmuls (term-major order)
    fused_lstm<<<NBLK, 256, SMEMB>>>(r1, k2, b2, r2, k3, b3, r3, k4, b4, r4, xk);
    // 4) dense head + softmax
    dense_head_kernel<<<BATCH, 256>>>(WD[0], BD[0], WD[1], BD[1], WD[2], BD[2],
                                      WD[3], BD[3], WD[4], BD[4], WD[5], BD[5],
                                      (float*)d_out);
}

// round 15
// speedup vs baseline: 1.4519x; 1.4519x over previous
#include <cuda_runtime.h>
#include <cuda_bf16.h>
#include <math.h>

#define BATCH 128
#define SEQT  512
#define TSTEPS 518   // 512 + 6 pipeline offsets
#define NBLK 148

// ---- device-global scratch (allocation-free rule) ----
__device__ float g_xk[(size_t)BATCH * SEQT * 2560];  // layer-1 input proj [T][4][640][B] fp32
// split-bf16 hidden state, k-pair packed: u32 = bf16(k even) | bf16(k odd)<<16
// layout [par][kpair][B]; kpair offsets: l1 0, l2 320, l3 520, l4 648; total 776
__device__ unsigned int g_h2hi[2][776 * 128];
__device__ unsigned int g_h2lo[2][776 * 128];
__device__ float g_cbuf[1552 * 128];                 // fp32 cell state, j offsets 0/640/1040/1296
__device__ float g_xkbuf[2][3648 * 128];             // proj outputs fp32, offsets l2 0, l3 1600, l4 2624
__device__ unsigned int g_bar;

// ---- packed f32x2 helpers (used by the standalone gemm) ----
__device__ __forceinline__ unsigned long long pack2(float x, float y) {
    unsigned long long d;
    asm("mov.b64 %0, {%1, %2};" : "=l"(d) : "f"(x), "f"(y));
    return d;
}
__device__ __forceinline__ unsigned long long ffma2(unsigned long long a,
                                                    unsigned long long b,
                                                    unsigned long long c) {
    unsigned long long d;
    asm("fma.rn.f32x2 %0, %1, %2, %3;" : "=l"(d) : "l"(a), "l"(b), "l"(c));
    return d;
}
__device__ __forceinline__ void unpack2(unsigned long long v, float& lo, float& hi) {
    asm("mov.b64 {%0, %1}, %2;" : "=f"(lo), "=f"(hi) : "l"(v));
}
__device__ __forceinline__ float sigf(float v) { return 1.f / (1.f + expf(-v)); }

__device__ __forceinline__ int kpbase(int l) {
    return (l == 1) ? 0 : (l == 2) ? 320 : (l == 3) ? 520 : 648;
}
__device__ __forceinline__ float* cbuf_ptr(int l) {
    const int off = (l == 1) ? 0 : (l == 2) ? 640 : (l == 3) ? 1040 : 1296;
    return g_cbuf + (size_t)off * 128;
}
__device__ __forceinline__ float* xkb_ptr(int par, int l) {
    const int off = (l == 2) ? 0 : (l == 3) ? 1600 : 2624;
    return g_xkbuf[par] + (size_t)off * 128;
}

// bf16 mma: D += A(16x16) * B(16x8), A row-major frag, B col-major frag, f32 acc
__device__ __forceinline__ void mma_bf16(float* d,
                                         unsigned a0, unsigned a1, unsigned a2, unsigned a3,
                                         unsigned b0, unsigned b1) {
    asm volatile("mma.sync.aligned.m16n8k16.row.col.f32.bf16.bf16.f32 "
                 "{%0,%1,%2,%3}, {%4,%5,%6,%7}, {%8,%9}, {%0,%1,%2,%3};"
                 : "+f"(d[0]), "+f"(d[1]), "+f"(d[2]), "+f"(d[3])
                 : "r"(a0), "r"(a1), "r"(a2), "r"(a3), "r"(b0), "r"(b1));
}

// ---- reset state before wavefront ----
__global__ void reset_all() {
    size_t i = (size_t)blockIdx.x * blockDim.x + threadIdx.x;
    const size_t N1 = (size_t)2 * 776 * 128;   // 198656
    if (i < N1) { (&g_h2hi[0][0])[i] = 0u; (&g_h2lo[0][0])[i] = 0u; }
    if (i < (size_t)1552 * 128) g_cbuf[i] = 0.f;
    if (i == 0) g_bar = 0u;
}

// ---- layer-1 input-projection GEMM: x[B][T][64] @ k1 -> g_xk [t][4][640][B] fp32 ----
__global__ void gemm_bias_kernel(const float* __restrict__ A, const float* __restrict__ W,
                                 const float* __restrict__ bias, float* __restrict__ C,
                                 int M, int N, int K) {
    __shared__ float As[16][64];
    __shared__ float Ws[16][64];
    const int H = N >> 2;
    int tid = threadIdx.x;
    int n0 = blockIdx.x * 64, m0 = blockIdx.y * 64;
    int tn = tid & 15, tm = tid >> 4;
    int ak = tid & 15, am = tid >> 4;
    int wn = tid & 63, wk = tid >> 6;

    unsigned long long acc01[4], acc23[4];
#pragma unroll
    for (int i = 0; i < 4; i++) { acc01[i] = pack2(0.f, 0.f); acc23[i] = acc01[i]; }

    size_t srow[4];
#pragma unroll
    for (int i = 0; i < 4; i++) {
        int m = m0 + am + i * 16;
        srow[i] = (size_t)(m % BATCH) * SEQT + (size_t)(m / BATCH);
    }

    for (int k0 = 0; k0 < K; k0 += 16) {
#pragma unroll
        for (int i = 0; i < 4; i++)
            As[ak][am + i * 16] = A[srow[i] * K + k0 + ak];
#pragma unroll
        for (int i = 0; i < 4; i++)
            Ws[wk + i * 4][wn] = W[(size_t)(k0 + wk + i * 4) * N + n0 + wn];
        __syncthreads();
#pragma unroll
        for (int k = 0; k < 16; k++) {
            float4 a4 = *(const float4*)&As[k][tm * 4];
            float4 w4 = *(const float4*)&Ws[k][tn * 4];
            unsigned long long a01 = pack2(a4.x, a4.y);
            unsigned long long a23 = pack2(a4.z, a4.w);
            float warr[4] = {w4.x, w4.y, w4.z, w4.w};
#pragma unroll
            for (int j4 = 0; j4 < 4; j4++) {
                unsigned long long wd = pack2(warr[j4], warr[j4]);
                acc01[j4] = ffma2(a01, wd, acc01[j4]);
                acc23[j4] = ffma2(a23, wd, acc23[j4]);
            }
        }
        __syncthreads();
    }
    int t = m0 >> 7;
    int bb = (m0 & 127) + tm * 4;
#pragma unroll
    for (int j4 = 0; j4 < 4; j4++) {
        int n = n0 + tn * 4 + j4;
        int g = n / H;
        int jj = n - g * H;
        float bn = bias[n];
        float v0, v1, v2, v3;
        unpack2(acc01[j4], v0, v1);
        unpack2(acc23[j4], v2, v3);
        *(float4*)&C[((size_t)(t * 4 + g) * H + jj) * 128 + bb] =
            make_float4(v0 + bn, v1 + bn, v2 + bn, v3 + bn);
    }
}

// ---- grid barrier (148 blocks, 1/SM guaranteed by smem) ----
__device__ __forceinline__ void grid_sync(unsigned int target) {
    __threadfence();
    __syncthreads();
    if (threadIdx.x == 0) {
        atomicAdd(&g_bar, 1u);
        unsigned int v;
        do {
            asm volatile("ld.acquire.gpu.u32 %0, [%1];" : "=r"(v) : "l"(&g_bar));
        } while (v < target);
    }
    __syncthreads();
}

// ---- wavefront persistent loop with split-bf16 MMA ----
// 256 threads = 8 warps; warp w owns batch rows 16w..16w+15 (A frags never shared
// across warps -> NO smem staging, NO per-chunk syncs). Each warp gathers its A
// fragments straight from global (L2-resident h) with one-chunk register prefetch.
// Weights resident in smem as [n][KPW] k-pair u32 hi/lo. 3 MMAs per tile (split-bf16).
template<int MAXNT>
__device__ __forceinline__ void persist_loop(
    int isrec, int layer, int Hin, int Hout, int ntiles, int jstart, int toff,
    const float* __restrict__ bias,
    const unsigned int* __restrict__ wsmHi, const unsigned int* __restrict__ wsmLo,
    float* __restrict__ zbuf, int KPW,
    const float* __restrict__ xk1)
{
    const int tid = threadIdx.x;
    const int lane = tid & 31, w = tid >> 5;
    const int r = lane >> 2, cc = lane & 3;
    const unsigned int nb = gridDim.x;
    const int NKC = Hin >> 4;
    const int srcl = isrec ? layer : layer - 1;
    const int srcKp = kpbase(srcl);
    const int dstKp = kpbase(layer);
    float* cst = cbuf_ptr(layer);
    const int abi = 16 * w + r;          // this lane's A-fragment batch row

    for (int s = 0; s < TSTEPS; s++) {
        int t = s - toff;
        if (t >= 0 && t < SEQT) {
            int par = t & 1;
            int spar = isrec ? (par ^ 1) : par;
            const unsigned int* hsHi = g_h2hi[spar] + (size_t)srcKp * 128;
            const unsigned int* hsLo = g_h2lo[spar] + (size_t)srcKp * 128;

            float acc[MAXNT][4];
#pragma unroll
            for (int nt = 0; nt < MAXNT; nt++) {
                acc[nt][0] = 0.f; acc[nt][1] = 0.f; acc[nt][2] = 0.f; acc[nt][3] = 0.f;
            }

            // A-fragment direct loads, one-chunk prefetch
            unsigned cH0, cH1, cH2, cH3, cL0, cL1, cL2, cL3;
            unsigned nH0, nH1, nH2, nH3, nL0, nL1, nL2, nL3;
            {
                int o0 = cc * 128 + abi, o1 = (cc + 4) * 128 + abi;
                cH0 = hsHi[o0]; cH1 = hsHi[o0 + 8]; cH2 = hsHi[o1]; cH3 = hsHi[o1 + 8];
                cL0 = hsLo[o0]; cL1 = hsLo[o0 + 8]; cL2 = hsLo[o1]; cL3 = hsLo[o1 + 8];
            }
            for (int c = 0; c < NKC; c++) {
                if (c + 1 < NKC) {
                    int base = (c + 1) * 8 * 128;
                    int o0 = base + cc * 128 + abi, o1 = base + (cc + 4) * 128 + abi;
                    nH0 = hsHi[o0]; nH1 = hsHi[o0 + 8]; nH2 = hsHi[o1]; nH3 = hsHi[o1 + 8];
                    nL0 = hsLo[o0]; nL1 = hsLo[o0 + 8]; nL2 = hsLo[o1]; nL3 = hsLo[o1 + 8];
                }
                int kp0 = c * 8;
#pragma unroll
                for (int nt = 0; nt < MAXNT; nt++) {
                    if (nt < ntiles) {
                        int n = nt * 8 + r;
                        unsigned bh0 = wsmHi[n * KPW + kp0 + cc];
                        unsigned bh1 = wsmHi[n * KPW + kp0 + cc + 4];
                        unsigned bl0 = wsmLo[n * KPW + kp0 + cc];
                        unsigned bl1 = wsmLo[n * KPW + kp0 + cc + 4];
                        mma_bf16(acc[nt], cH0, cH1, cH2, cH3, bh0, bh1);
                        mma_bf16(acc[nt], cH0, cH1, cH2, cH3, bl0, bl1);
                        mma_bf16(acc[nt], cL0, cL1, cL2, cL3, bh0, bh1);
                    }
                }
                if (c + 1 < NKC) {
                    cH0 = nH0; cH1 = nH1; cH2 = nH2; cH3 = nH3;
                    cL0 = nL0; cL1 = nL1; cL2 = nL2; cL3 = nL3;
                }
            }

            // D fragments -> zbuf[n][b] (pitch 132)
#pragma unroll
            for (int nt = 0; nt < MAXNT; nt++) {
                if (nt < ntiles) {
                    int nb0 = nt * 8 + 2 * cc;
                    int br = 16 * w + r;
                    zbuf[nb0 * 132 + br] = acc[nt][0];
                    zbuf[(nb0 + 1) * 132 + br] = acc[nt][1];
                    zbuf[nb0 * 132 + br + 8] = acc[nt][2];
                    zbuf[(nb0 + 1) * 132 + br + 8] = acc[nt][3];
                }
            }
            __syncthreads();

            if (isrec) {
                const float* xsrc = (layer == 1) ? (xk1 + (size_t)t * 2560 * 128)
                                                 : xkb_ptr(par, layer);
                __nv_bfloat16* hh = (__nv_bfloat16*)(g_h2hi[par] + (size_t)dstKp * 128);
                __nv_bfloat16* hl = (__nv_bfloat16*)(g_h2lo[par] + (size_t)dstKp * 128);
#pragma unroll
                for (int e = 0; e < MAXNT; e++) {
                    if (e < ntiles) {
                        int idx = e * 256 + tid;
                        int jl = idx >> 7, b = idx & 127;
                        int jg = jstart + jl;
                        float zi = zbuf[(jl * 4 + 0) * 132 + b] + xsrc[(size_t)(0 * Hout + jg) * 128 + b];
                        float zf = zbuf[(jl * 4 + 1) * 132 + b] + xsrc[(size_t)(1 * Hout + jg) * 128 + b];
                        float zg = zbuf[(jl * 4 + 2) * 132 + b] + xsrc[(size_t)(2 * Hout + jg) * 128 + b];
                        float zo = zbuf[(jl * 4 + 3) * 132 + b] + xsrc[(size_t)(3 * Hout + jg) * 128 + b];
                        float ig = sigf(zi), fg = sigf(zf);
                        float gg = tanhf(zg), og = sigf(zo);
                        size_t ci = (size_t)jg * 128 + b;
                        float cn = fg * cst[ci] + ig * gg;
                        float h = og * tanhf(cn);
                        cst[ci] = cn;
                        __nv_bfloat16 hhi = __float2bfloat16(h);
                        __nv_bfloat16 hlo = __float2bfloat16(h - __bfloat162float(hhi));
                        size_t widx = ((size_t)(jg >> 1) * 128 + b) * 2 + (jg & 1);
                        hh[widx] = hhi;
                        hl[widx] = hlo;
                    }
                }
            } else {
                float* dst = xkb_ptr(par, layer);
#pragma unroll
                for (int e = 0; e < MAXNT; e++) {
                    if (e < ntiles) {
                        int idx = e * 256 + tid;
                        int jl = idx >> 7, b = idx & 127;
                        int jg = jstart + jl;
#pragma unroll
                        for (int g = 0; g < 4; g++)
                            dst[(size_t)(g * Hout + jg) * 128 + b] =
                                zbuf[(jl * 4 + g) * 132 + b] + bias[g * Hout + jg];
                    }
                }
            }
        }
        grid_sync((unsigned int)(s + 1) * nb);
    }
}

__global__ void __launch_bounds__(256, 1)
fused_lstm(const float* __restrict__ R1, const float* __restrict__ K2,
           const float* __restrict__ B2, const float* __restrict__ R2,
           const float* __restrict__ K3, const float* __restrict__ B3,
           const float* __restrict__ R3, const float* __restrict__ K4,
           const float* __restrict__ B4, const float* __restrict__ R4,
           const float* __restrict__ xk1) {
    extern __shared__ unsigned int smem[];

    // roles: 0 L1rec, 1 L2proj, 2 L2rec, 3 L3proj, 4 L3rec, 5 L4proj, 6 L4rec
    const int r_nb[7]    = {54, 34, 21, 13, 9, 9, 8};
    const int r_rec[7]   = {1, 0, 1, 0, 1, 0, 1};
    const int r_layer[7] = {1, 2, 2, 3, 3, 4, 4};
    const int r_Hin[7]   = {640, 640, 400, 400, 256, 256, 256};
    const int r_Hout[7]  = {640, 400, 400, 256, 256, 256, 256};
    const int r_tiles[7] = {320, 200, 200, 128, 128, 128, 128};

    int bid = blockIdx.x;
    int role = 0, start = 0;
    {
        int s2 = 0;
        for (int rr = 0; rr < 7; rr++) {
            if (bid >= s2 && bid < s2 + r_nb[rr]) { role = rr; start = s2; }
            s2 += r_nb[rr];
        }
    }
    int ridx = bid - start;
    const int Hin = r_Hin[role], Hout = r_Hout[role];
    const int layer = r_layer[role], isrec = r_rec[role];
    const int T = r_tiles[role];
    const int q = T / r_nb[role], rm = T % r_nb[role];
    const int ntiles = q + (ridx < rm ? 1 : 0);
    const int tstart = ridx * q + (ridx < rm ? ridx : rm);
    const int jstart = tstart * 2;
    const int kpairs = Hin >> 1;
    const int KPW = (Hin == 640) ? 324 : (Hin == 400) ? 228 : 132;
    const int Nn = ntiles * 8;

    unsigned int* wsmHi = smem;
    unsigned int* wsmLo = smem + (size_t)Nn * KPW;
    float* zbuf = (float*)(wsmLo + (size_t)Nn * KPW);

    const float* Wsel = (role == 0) ? R1 : (role == 1) ? K2 : (role == 2) ? R2
                       : (role == 3) ? K3 : (role == 4) ? R3 : (role == 5) ? K4 : R4;
    const float* bias = (role == 1) ? B2 : (role == 3) ? B3 : (role == 5) ? B4 : (const float*)0;

    // preamble: load fp32 weights, convert to split-bf16 k-pair u32 layout [n][KPW]
    {
        int tid = threadIdx.x;
        int tot = Nn * kpairs;
        for (int e = tid; e < tot; e += 256) {
            int n = e / kpairs, kp = e - n * kpairs;
            int jl = n >> 2, g = n & 3;
            int gcol = g * Hout + jstart + jl;
            float w0 = Wsel[(size_t)(2 * kp) * (4 * Hout) + gcol];
            float w1 = Wsel[(size_t)(2 * kp + 1) * (4 * Hout) + gcol];
            __nv_bfloat16 h0 = __float2bfloat16(w0);
            __nv_bfloat16 l0 = __float2bfloat16(w0 - __bfloat162float(h0));
            __nv_bfloat16 h1 = __float2bfloat16(w1);
            __nv_bfloat16 l1 = __float2bfloat16(w1 - __bfloat162float(h1));
            wsmHi[n * KPW + kp] = (unsigned)__bfloat16_as_ushort(h0)
                                | ((unsigned)__bfloat16_as_ushort(h1) << 16);
            wsmLo[n * KPW + kp] = (unsigned)__bfloat16_as_ushort(l0)
                                | ((unsigned)__bfloat16_as_ushort(l1) << 16);
        }
    }
    __syncthreads();

    if (role <= 1)
        persist_loop<6>(isrec, layer, Hin, Hout, ntiles, jstart, role, bias,
                        wsmHi, wsmLo, zbuf, KPW, xk1);
    else if (role <= 3)
        persist_loop<10>(isrec, layer, Hin, Hout, ntiles, jstart, role, bias,
                         wsmHi, wsmLo, zbuf, KPW, xk1);
    else
        persist_loop<16>(isrec, layer, Hin, Hout, ntiles, jstart, role, bias,
                         wsmHi, wsmLo, zbuf, KPW, xk1);
}

// ---- dense head: 6 FC layers + softmax; h4 from split-bf16 (par 1) ----
__device__ __forceinline__ void dense_layer(const float* __restrict__ W,
                                            const float* __restrict__ bi,
                                            const float* in, float* out2,
                                            int din, int dout, bool relu) {
    for (int j = threadIdx.x; j < dout; j += blockDim.x) {
        float s = bi[j];
        for (int kk = 0; kk < din; kk++) s += in[kk] * W[(size_t)kk * dout + j];
        out2[j] = relu ? fmaxf(s, 0.f) : s;
    }
    __syncthreads();
}

__global__ void dense_head_kernel(const float* w1, const float* b1,
                                  const float* w2, const float* b2,
                                  const float* w3, const float* b3,
                                  const float* w4, const float* b4,
                                  const float* w5, const float* b5,
                                  const float* w6, const float* b6,
                                  float* __restrict__ out) {
    __shared__ float bufa[512], bufb[512];
    int b = blockIdx.x;
    const __nv_bfloat16* hh = (const __nv_bfloat16*)(g_h2hi[1] + (size_t)648 * 128);
    const __nv_bfloat16* hl = (const __nv_bfloat16*)(g_h2lo[1] + (size_t)648 * 128);
    for (int j = threadIdx.x; j < 256; j += blockDim.x) {
        size_t widx = ((size_t)(j >> 1) * 128 + b) * 2 + (j & 1);
        bufa[j] = __bfloat162float(hh[widx]) + __bfloat162float(hl[widx]);
    }
    __syncthreads();
    dense_layer(w1, b1, bufa, bufb, 256, 512, true);
    dense_layer(w2, b2, bufb, bufa, 512, 256, true);
    dense_layer(w3, b3, bufa, bufb, 256, 128, true);
    dense_layer(w4, b4, bufb, bufa, 128, 64, true);
    dense_layer(w5, b5, bufa, bufb, 64, 16, true);
    dense_layer(w6, b6, bufb, bufa, 16, 3, false);
    if (threadIdx.x == 0) {
        float m = fmaxf(bufa[0], fmaxf(bufa[1], bufa[2]));
        float e0 = expf(bufa[0] - m), e1 = expf(bufa[1] - m), e2 = expf(bufa[2] - m);
        float s = e0 + e1 + e2;
        out[b * 3 + 0] = e0 / s;
        out[b * 3 + 1] = e1 / s;
        out[b * 3 + 2] = e2 / s;
    }
}

extern "C" void kernel_launch(void* const* d_in, const int* in_sizes, int n_in,
                              void* d_out, int out_size) {
    const float* x  = (const float*)d_in[0];
    const float* k1 = (const float*)d_in[1];
    const float* r1 = (const float*)d_in[2];
    const float* b1 = (const float*)d_in[3];
    const float* k2 = (const float*)d_in[4];
    const float* r2 = (const float*)d_in[5];
    const float* b2 = (const float*)d_in[6];
    const float* k3 = (const float*)d_in[7];
    const float* r3 = (const float*)d_in[8];
    const float* b3 = (const float*)d_in[9];
    const float* k4 = (const float*)d_in[10];
    const float* r4 = (const float*)d_in[11];
    const float* b4 = (const float*)d_in[12];
    const float* WD[6];
    const float* BD[6];
    for (int i = 0; i < 6; i++) {
        WD[i] = (const float*)d_in[13 + 2 * i];
        BD[i] = (const float*)d_in[14 + 2 * i];
    }

    float* xk;
    cudaGetSymbolAddress((void**)&xk, g_xk);

    // max smem over roles: role6 = 128*132*2*4 (weights) + 128*132*4 (zbuf) = 202752 B
    const int SMEMB = 205824;
    cudaFuncSetAttribute(fused_lstm, cudaFuncAttributeMaxDynamicSharedMemorySize, SMEMB);

    const int M = BATCH * SEQT;

    // 1) layer-1 input projection GEMM (fp32)
    gemm_bias_kernel<<<dim3(2560 / 64, M / 64), 256>>>(x, k1, b1, xk, M, 2560, 64);
    // 2) zero h/c/barrier
    reset_all<<<776, 256>>>();
    // 3) fused 4-layer wavefront, split-bf16 MMA, direct-LDG A frags (no staging syncs)
    fused_lstm<<<NBLK, 256, SMEMB>>>(r1, k2, b2, r2, k3, b3, r3, k4, b4, r4, xk);
    // 4) dense head + softmax
    dense_head_kernel<<<BATCH, 256>>>(WD[0], BD[0], WD[1], BD[1], WD[2], BD[2],
                                      WD[3], BD[3], WD[4], BD[4], WD[5], BD[5],
                                      (float*)d_out);
}

// round 16
// speedup vs baseline: 1.5929x; 1.0971x over previous
#include <cuda_runtime.h>
#include <cuda_fp16.h>
#include <math.h>

#define BATCH 128
#define SEQT  512
#define TSTEPS 518   // 512 + 6 pipeline offsets
#define NBLK 148

// ---- device-global scratch (allocation-free rule) ----
__device__ float g_xk[(size_t)BATCH * SEQT * 2560];  // layer-1 input proj [T][4][640][B] fp32
// split-fp16 hidden state, k-pair packed: u32 = fp16(k even) | fp16(k odd)<<16
// layout [par][kpair][B]; kpair offsets: l1 0, l2 320, l3 520, l4 648; total 776
__device__ unsigned int g_h2hi[2][776 * 128];
__device__ unsigned int g_h2lo[2][776 * 128];
__device__ float g_cbuf[1552 * 128];                 // fp32 cell state, j offsets 0/640/1040/1296
__device__ float g_xkbuf[2][3648 * 128];             // proj outputs fp32, offsets l2 0, l3 1600, l4 2624
__device__ unsigned int g_bar;

// ---- packed f32x2 helpers (used by the standalone gemm) ----
__device__ __forceinline__ unsigned long long pack2(float x, float y) {
    unsigned long long d;
    asm("mov.b64 %0, {%1, %2};" : "=l"(d) : "f"(x), "f"(y));
    return d;
}
__device__ __forceinline__ unsigned long long ffma2(unsigned long long a,
                                                    unsigned long long b,
                                                    unsigned long long c) {
    unsigned long long d;
    asm("fma.rn.f32x2 %0, %1, %2, %3;" : "=l"(d) : "l"(a), "l"(b), "l"(c));
    return d;
}
__device__ __forceinline__ void unpack2(unsigned long long v, float& lo, float& hi) {
    asm("mov.b64 {%0, %1}, %2;" : "=f"(lo), "=f"(hi) : "l"(v));
}
__device__ __forceinline__ float sigf(float v) { return 1.f / (1.f + expf(-v)); }

__device__ __forceinline__ int kpbase(int l) {
    return (l == 1) ? 0 : (l == 2) ? 320 : (l == 3) ? 520 : 648;
}
__device__ __forceinline__ float* cbuf_ptr(int l) {
    const int off = (l == 1) ? 0 : (l == 2) ? 640 : (l == 3) ? 1040 : 1296;
    return g_cbuf + (size_t)off * 128;
}
__device__ __forceinline__ float* xkb_ptr(int par, int l) {
    const int off = (l == 2) ? 0 : (l == 3) ? 1600 : 2624;
    return g_xkbuf[par] + (size_t)off * 128;
}

// fp16 mma: D += A(16x16) * B(16x8), A row-major frag, B col-major frag, f32 acc
__device__ __forceinline__ void mma_f16(float* d,
                                        unsigned a0, unsigned a1, unsigned a2, unsigned a3,
                                        unsigned b0, unsigned b1) {
    asm volatile("mma.sync.aligned.m16n8k16.row.col.f32.f16.f16.f32 "
                 "{%0,%1,%2,%3}, {%4,%5,%6,%7}, {%8,%9}, {%0,%1,%2,%3};"
                 : "+f"(d[0]), "+f"(d[1]), "+f"(d[2]), "+f"(d[3])
                 : "r"(a0), "r"(a1), "r"(a2), "r"(a3), "r"(b0), "r"(b1));
}

// ---- reset state before wavefront ----
__global__ void reset_all() {
    size_t i = (size_t)blockIdx.x * blockDim.x + threadIdx.x;
    const size_t N1 = (size_t)2 * 776 * 128;   // 198656
    if (i < N1) { (&g_h2hi[0][0])[i] = 0u; (&g_h2lo[0][0])[i] = 0u; }
    if (i < (size_t)1552 * 128) g_cbuf[i] = 0.f;
    if (i == 0) g_bar = 0u;
}

// ---- layer-1 input-projection GEMM: x[B][T][64] @ k1 -> g_xk [t][4][640][B] fp32 ----
__global__ void gemm_bias_kernel(const float* __restrict__ A, const float* __restrict__ W,
                                 const float* __restrict__ bias, float* __restrict__ C,
                                 int M, int N, int K) {
    __shared__ float As[16][64];
    __shared__ float Ws[16][64];
    const int H = N >> 2;
    int tid = threadIdx.x;
    int n0 = blockIdx.x * 64, m0 = blockIdx.y * 64;
    int tn = tid & 15, tm = tid >> 4;
    int ak = tid & 15, am = tid >> 4;
    int wn = tid & 63, wk = tid >> 6;

    unsigned long long acc01[4], acc23[4];
#pragma unroll
    for (int i = 0; i < 4; i++) { acc01[i] = pack2(0.f, 0.f); acc23[i] = acc01[i]; }

    size_t srow[4];
#pragma unroll
    for (int i = 0; i < 4; i++) {
        int m = m0 + am + i * 16;
        srow[i] = (size_t)(m % BATCH) * SEQT + (size_t)(m / BATCH);
    }

    for (int k0 = 0; k0 < K; k0 += 16) {
#pragma unroll
        for (int i = 0; i < 4; i++)
            As[ak][am + i * 16] = A[srow[i] * K + k0 + ak];
#pragma unroll
        for (int i = 0; i < 4; i++)
            Ws[wk + i * 4][wn] = W[(size_t)(k0 + wk + i * 4) * N + n0 + wn];
        __syncthreads();
#pragma unroll
        for (int k = 0; k < 16; k++) {
            float4 a4 = *(const float4*)&As[k][tm * 4];
            float4 w4 = *(const float4*)&Ws[k][tn * 4];
            unsigned long long a01 = pack2(a4.x, a4.y);
            unsigned long long a23 = pack2(a4.z, a4.w);
            float warr[4] = {w4.x, w4.y, w4.z, w4.w};
#pragma unroll
            for (int j4 = 0; j4 < 4; j4++) {
                unsigned long long wd = pack2(warr[j4], warr[j4]);
                acc01[j4] = ffma2(a01, wd, acc01[j4]);
                acc23[j4] = ffma2(a23, wd, acc23[j4]);
            }
        }
        __syncthreads();
    }
    int t = m0 >> 7;
    int bb = (m0 & 127) + tm * 4;
#pragma unroll
    for (int j4 = 0; j4 < 4; j4++) {
        int n = n0 + tn * 4 + j4;
        int g = n / H;
        int jj = n - g * H;
        float bn = bias[n];
        float v0, v1, v2, v3;
        unpack2(acc01[j4], v0, v1);
        unpack2(acc23[j4], v2, v3);
        *(float4*)&C[((size_t)(t * 4 + g) * H + jj) * 128 + bb] =
            make_float4(v0 + bn, v1 + bn, v2 + bn, v3 + bn);
    }
}

// ---- grid barrier (148 blocks, 1/SM guaranteed by smem); tid0-only fence ----
__device__ __forceinline__ void grid_sync(unsigned int target) {
    __syncthreads();
    if (threadIdx.x == 0) {
        __threadfence();
        atomicAdd(&g_bar, 1u);
        unsigned int v;
        do {
            asm volatile("ld.acquire.gpu.u32 %0, [%1];" : "=r"(v) : "l"(&g_bar));
        } while (v < target);
    }
    __syncthreads();
}

// ---- wavefront persistent loop with split-fp16 MMA (2 MMAs/tile) ----
// 256 threads = 8 warps; warp w owns batch rows 16w..16w+15.
// A (h) staged per k16 chunk as k-pair u32 [8][136] hi/lo, double buffered.
// Weights resident in smem as SINGLE fp16 plane [n][KPW] k-pair u32.
// Per tile: acc += A_hi*B ; acc += A_lo*B  (A split to ~21 bits, B 11 bits).
template<int MAXNT>
__device__ __forceinline__ void persist_loop(
    int isrec, int layer, int Hin, int Hout, int ntiles, int jstart, int toff,
    const float* __restrict__ bias,
    const unsigned int* __restrict__ wsm,
    unsigned int* __restrict__ bufA, float* __restrict__ zbuf, int KPW,
    const float* __restrict__ xk1)
{
    const int tid = threadIdx.x;
    const int lane = tid & 31, w = tid >> 5;
    const int r = lane >> 2, cc = lane & 3;
    const unsigned int nb = gridDim.x;
    const int NKC = Hin >> 4;
    const int srcl = isrec ? layer : layer - 1;
    const int srcKp = kpbase(srcl);
    const int dstKp = kpbase(layer);
    float* cst = cbuf_ptr(layer);
    const int klq = tid >> 5;            // staging row 0..7
    const int bq = (tid & 31) * 4;       // staging col

    for (int s = 0; s < TSTEPS; s++) {
        int t = s - toff;
        if (t >= 0 && t < SEQT) {
            int par = t & 1;
            int spar = isrec ? (par ^ 1) : par;
            const unsigned int* hsHi = g_h2hi[spar] + (size_t)srcKp * 128;
            const unsigned int* hsLo = g_h2lo[spar] + (size_t)srcKp * 128;

            float acc[MAXNT][4];
#pragma unroll
            for (int nt = 0; nt < MAXNT; nt++) {
                acc[nt][0] = 0.f; acc[nt][1] = 0.f; acc[nt][2] = 0.f; acc[nt][3] = 0.f;
            }

            // stage chunk 0
            uint4 pfh = *(const uint4*)(hsHi + tid * 4);
            uint4 pfl = *(const uint4*)(hsLo + tid * 4);
            *(uint4*)(bufA + klq * 136 + bq) = pfh;
            *(uint4*)(bufA + 1088 + klq * 136 + bq) = pfl;
            __syncthreads();
            if (NKC > 1) {
                pfh = *(const uint4*)(hsHi + 1024 + tid * 4);
                pfl = *(const uint4*)(hsLo + 1024 + tid * 4);
            }

            for (int c = 0; c < NKC; c++) {
                const unsigned int* bh = bufA + (c & 1) * 2176;
                const unsigned int* bl = bh + 1088;
                unsigned ah0 = bh[cc * 136 + 16 * w + r];
                unsigned ah1 = bh[cc * 136 + 16 * w + r + 8];
                unsigned ah2 = bh[(cc + 4) * 136 + 16 * w + r];
                unsigned ah3 = bh[(cc + 4) * 136 + 16 * w + r + 8];
                unsigned al0 = bl[cc * 136 + 16 * w + r];
                unsigned al1 = bl[cc * 136 + 16 * w + r + 8];
                unsigned al2 = bl[(cc + 4) * 136 + 16 * w + r];
                unsigned al3 = bl[(cc + 4) * 136 + 16 * w + r + 8];
                int kp0 = c * 8;
#pragma unroll
                for (int nt = 0; nt < MAXNT; nt++) {
                    if (nt < ntiles) {
                        int n = nt * 8 + r;
                        unsigned b0 = wsm[n * KPW + kp0 + cc];
                        unsigned b1 = wsm[n * KPW + kp0 + cc + 4];
                        mma_f16(acc[nt], ah0, ah1, ah2, ah3, b0, b1);
                        mma_f16(acc[nt], al0, al1, al2, al3, b0, b1);
                    }
                }
                if (c + 1 < NKC) {
                    unsigned int* dh = bufA + ((c + 1) & 1) * 2176;
                    *(uint4*)(dh + klq * 136 + bq) = pfh;
                    *(uint4*)(dh + 1088 + klq * 136 + bq) = pfl;
                    __syncthreads();
                    if (c + 2 < NKC) {
                        pfh = *(const uint4*)(hsHi + (size_t)(c + 2) * 1024 + tid * 4);
                        pfl = *(const uint4*)(hsLo + (size_t)(c + 2) * 1024 + tid * 4);
                    }
                }
            }

            // D fragments -> zbuf[n][b] (pitch 132)
#pragma unroll
            for (int nt = 0; nt < MAXNT; nt++) {
                if (nt < ntiles) {
                    int nb0 = nt * 8 + 2 * cc;
                    int br = 16 * w + r;
                    zbuf[nb0 * 132 + br] = acc[nt][0];
                    zbuf[(nb0 + 1) * 132 + br] = acc[nt][1];
                    zbuf[nb0 * 132 + br + 8] = acc[nt][2];
                    zbuf[(nb0 + 1) * 132 + br + 8] = acc[nt][3];
                }
            }
            __syncthreads();

            if (isrec) {
                const float* xsrc = (layer == 1) ? (xk1 + (size_t)t * 2560 * 128)
                                                 : xkb_ptr(par, layer);
                unsigned short* hh = (unsigned short*)(g_h2hi[par] + (size_t)dstKp * 128);
                unsigned short* hl = (unsigned short*)(g_h2lo[par] + (size_t)dstKp * 128);
#pragma unroll
                for (int e = 0; e < MAXNT; e++) {
                    if (e < ntiles) {
                        int idx = e * 256 + tid;
                        int jl = idx >> 7, b = idx & 127;
                        int jg = jstart + jl;
                        float zi = zbuf[(jl * 4 + 0) * 132 + b] + xsrc[(size_t)(0 * Hout + jg) * 128 + b];
                        float zf = zbuf[(jl * 4 + 1) * 132 + b] + xsrc[(size_t)(1 * Hout + jg) * 128 + b];
                        float zg = zbuf[(jl * 4 + 2) * 132 + b] + xsrc[(size_t)(2 * Hout + jg) * 128 + b];
                        float zo = zbuf[(jl * 4 + 3) * 132 + b] + xsrc[(size_t)(3 * Hout + jg) * 128 + b];
                        float ig = sigf(zi), fg = sigf(zf);
                        float gg = tanhf(zg), og = sigf(zo);
                        size_t ci = (size_t)jg * 128 + b;
                        float cn = fg * cst[ci] + ig * gg;
                        float h = og * tanhf(cn);
                        cst[ci] = cn;
                        __half hhi = __float2half_rn(h);
                        __half hlo = __float2half_rn(h - __half2float(hhi));
                        size_t widx = ((size_t)(jg >> 1) * 128 + b) * 2 + (jg & 1);
                        hh[widx] = __half_as_ushort(hhi);
                        hl[widx] = __half_as_ushort(hlo);
                    }
                }
            } else {
                float* dst = xkb_ptr(par, layer);
#pragma unroll
                for (int e = 0; e < MAXNT; e++) {
                    if (e < ntiles) {
                        int idx = e * 256 + tid;
                        int jl = idx >> 7, b = idx & 127;
                        int jg = jstart + jl;
#pragma unroll
                        for (int g = 0; g < 4; g++)
                            dst[(size_t)(g * Hout + jg) * 128 + b] =
                                zbuf[(jl * 4 + g) * 132 + b] + bias[g * Hout + jg];
                    }
                }
            }
        }
        grid_sync((unsigned int)(s + 1) * nb);
    }
}

__global__ void __launch_bounds__(256, 1)
fused_lstm(const float* __restrict__ R1, const float* __restrict__ K2,
           const float* __restrict__ B2, const float* __restrict__ R2,
           const float* __restrict__ K3, const float* __restrict__ B3,
           const float* __restrict__ R3, const float* __restrict__ K4,
           const float* __restrict__ B4, const float* __restrict__ R4,
           const float* __restrict__ xk1) {
    extern __shared__ unsigned int smem[];

    // roles: 0 L1rec, 1 L2proj, 2 L2rec, 3 L3proj, 4 L3rec, 5 L4proj, 6 L4rec
    const int r_nb[7]    = {54, 34, 21, 13, 9, 9, 8};
    const int r_rec[7]   = {1, 0, 1, 0, 1, 0, 1};
    const int r_layer[7] = {1, 2, 2, 3, 3, 4, 4};
    const int r_Hin[7]   = {640, 640, 400, 400, 256, 256, 256};
    const int r_Hout[7]  = {640, 400, 400, 256, 256, 256, 256};
    const int r_tiles[7] = {320, 200, 200, 128, 128, 128, 128};

    int bid = blockIdx.x;
    int role = 0, start = 0;
    {
        int s2 = 0;
        for (int rr = 0; rr < 7; rr++) {
            if (bid >= s2 && bid < s2 + r_nb[rr]) { role = rr; start = s2; }
            s2 += r_nb[rr];
        }
    }
    int ridx = bid - start;
    const int Hin = r_Hin[role], Hout = r_Hout[role];
    const int layer = r_layer[role], isrec = r_rec[role];
    const int T = r_tiles[role];
    const int q = T / r_nb[role], rm = T % r_nb[role];
    const int ntiles = q + (ridx < rm ? 1 : 0);
    const int tstart = ridx * q + (ridx < rm ? ridx : rm);
    const int jstart = tstart * 2;
    const int kpairs = Hin >> 1;
    const int KPW = (Hin == 640) ? 324 : (Hin == 400) ? 228 : 132;
    const int Nn = ntiles * 8;

    unsigned int* wsm = smem;
    unsigned int* bufA = smem + (size_t)Nn * KPW;
    float* zbuf = (float*)(bufA + 4352);

    const float* Wsel = (role == 0) ? R1 : (role == 1) ? K2 : (role == 2) ? R2
                       : (role == 3) ? K3 : (role == 4) ? R3 : (role == 5) ? K4 : R4;
    const float* bias = (role == 1) ? B2 : (role == 3) ? B3 : (role == 5) ? B4 : (const float*)0;

    // preamble: load fp32 weights, convert to single-fp16 k-pair u32 layout [n][KPW]
    {
        int tid = threadIdx.x;
        int tot = Nn * kpairs;
        for (int e = tid; e < tot; e += 256) {
            int n = e / kpairs, kp = e - n * kpairs;
            int jl = n >> 2, g = n & 3;
            int gcol = g * Hout + jstart + jl;
            float w0 = Wsel[(size_t)(2 * kp) * (4 * Hout) + gcol];
            float w1 = Wsel[(size_t)(2 * kp + 1) * (4 * Hout) + gcol];
            unsigned u0 = (unsigned)__half_as_ushort(__float2half_rn(w0));
            unsigned u1 = (unsigned)__half_as_ushort(__float2half_rn(w1));
            wsm[n * KPW + kp] = u0 | (u1 << 16);
        }
    }
    __syncthreads();

    if (role <= 1)
        persist_loop<6>(isrec, layer, Hin, Hout, ntiles, jstart, role, bias,
                        wsm, bufA, zbuf, KPW, xk1);
    else if (role <= 3)
        persist_loop<10>(isrec, layer, Hin, Hout, ntiles, jstart, role, bias,
                         wsm, bufA, zbuf, KPW, xk1);
    else
        persist_loop<16>(isrec, layer, Hin, Hout, ntiles, jstart, role, bias,
                         wsm, bufA, zbuf, KPW, xk1);
}

// ---- dense head: 6 FC layers + softmax; h4 from split-fp16 (par 1) ----
__device__ __forceinline__ void dense_layer(const float* __restrict__ W,
                                            const float* __restrict__ bi,
                                            const float* in, float* out2,
                                            int din, int dout, bool relu) {
    for (int j = threadIdx.x; j < dout; j += blockDim.x) {
        float s = bi[j];
        for (int kk = 0; kk < din; kk++) s += in[kk] * W[(size_t)kk * dout + j];
        out2[j] = relu ? fmaxf(s, 0.f) : s;
    }
    __syncthreads();
}

__global__ void dense_head_kernel(const float* w1, const float* b1,
                                  const float* w2, const float* b2,
                                  const float* w3, const float* b3,
                                  const float* w4, const float* b4,
                                  const float* w5, const float* b5,
                                  const float* w6, const float* b6,
                                  float* __restrict__ out) {
    __shared__ float bufa[512], bufb[512];
    int b = blockIdx.x;
    const unsigned short* hh = (const unsigned short*)(g_h2hi[1] + (size_t)648 * 128);
    const unsigned short* hl = (const unsigned short*)(g_h2lo[1] + (size_t)648 * 128);
    for (int j = threadIdx.x; j < 256; j += blockDim.x) {
        size_t widx = ((size_t)(j >> 1) * 128 + b) * 2 + (j & 1);
        bufa[j] = __half2float(__ushort_as_half(hh[widx]))
                + __half2float(__ushort_as_half(hl[widx]));
    }
    __syncthreads();
    dense_layer(w1, b1, bufa, bufb, 256, 512, true);
    dense_layer(w2, b2, bufb, bufa, 512, 256, true);
    dense_layer(w3, b3, bufa, bufb, 256, 128, true);
    dense_layer(w4, b4, bufb, bufa, 128, 64, true);
    dense_layer(w5, b5, bufa, bufb, 64, 16, true);
    dense_layer(w6, b6, bufb, bufa, 16, 3, false);
    if (threadIdx.x == 0) {
        float m = fmaxf(bufa[0], fmaxf(bufa[1], bufa[2]));
        float e0 = expf(bufa[0] - m), e1 = expf(bufa[1] - m), e2 = expf(bufa[2] - m);
        float s = e0 + e1 + e2;
        out[b * 3 + 0] = e0 / s;
        out[b * 3 + 1] = e1 / s;
        out[b * 3 + 2] = e2 / s;
    }
}

extern "C" void kernel_launch(void* const* d_in, const int* in_sizes, int n_in,
                              void* d_out, int out_size) {
    const float* x  = (const float*)d_in[0];
    const float* k1 = (const float*)d_in[1];
    const float* r1 = (const float*)d_in[2];
    const float* b1 = (const float*)d_in[3];
    const float* k2 = (const float*)d_in[4];
    const float* r2 = (const float*)d_in[5];
    const float* b2 = (const float*)d_in[6];
    const float* k3 = (const float*)d_in[7];
    const float* r3 = (const float*)d_in[8];
    const float* b3 = (const float*)d_in[9];
    const float* k4 = (const float*)d_in[10];
    const float* r4 = (const float*)d_in[11];
    const float* b4 = (const float*)d_in[12];
    const float* WD[6];
    const float* BD[6];
    for (int i = 0; i < 6; i++) {
        WD[i] = (const float*)d_in[13 + 2 * i];
        BD[i] = (const float*)d_in[14 + 2 * i];
    }

    float* xk;
    cudaGetSymbolAddress((void**)&xk, g_xk);

    // max smem over roles: role6 = (128*132 + 4352)*4 + 128*132*4 = 152576 B
    const int SMEMB = 155648;
    cudaFuncSetAttribute(fused_lstm, cudaFuncAttributeMaxDynamicSharedMemorySize, SMEMB);

    const int M = BATCH * SEQT;

    // 1) layer-1 input projection GEMM (fp32)
    gemm_bias_kernel<<<dim3(2560 / 64, M / 64), 256>>>(x, k1, b1, xk, M, 2560, 64);
    // 2) zero h/c/barrier
    reset_all<<<776, 256>>>();
    // 3) fused 4-layer wavefront, split-fp16 tensor-core matmuls (2 MMAs/tile)
    fused_lstm<<<NBLK, 256, SMEMB>>>(r1, k2, b2, r2, k3, b3, r3, k4, b4, r4, xk);
    // 4) dense head + softmax
    dense_head_kernel<<<BATCH, 256>>>(WD[0], BD[0], WD[1], BD[1], WD[2], BD[2],
                                      WD[3], BD[3], WD[4], BD[4], WD[5], BD[5],
                                      (float*)d_out);
}

// round 17
// speedup vs baseline: 1.7480x; 1.0973x over previous
#include <cuda_runtime.h>
#include <cuda_fp16.h>
#include <math.h>

#define BATCH 128
#define SEQT  512
#define TSTEPS 518   // 512 + 6 pipeline offsets
#define NBLK 148

// ---- device-global scratch (allocation-free rule) ----
__device__ float g_xk[(size_t)BATCH * SEQT * 2560];  // layer-1 input proj [T][4][640][B] fp32
// fp16 hidden state, k-pair packed: u32 = fp16(k even) | fp16(k odd)<<16
// layout [par][kpair][B]; kpair offsets: l1 0, l2 320, l3 520, l4 648; total 776
__device__ unsigned int g_h2[2][776 * 128];
__device__ float g_cbuf[1552 * 128];                 // fp32 cell state, j offsets 0/640/1040/1296
__device__ float g_xkbuf[2][3648 * 128];             // proj outputs fp32, offsets l2 0, l3 1600, l4 2624
__device__ unsigned int g_bar;

// ---- packed f32x2 helpers (used by the standalone gemm) ----
__device__ __forceinline__ unsigned long long pack2(float x, float y) {
    unsigned long long d;
    asm("mov.b64 %0, {%1, %2};" : "=l"(d) : "f"(x), "f"(y));
    return d;
}
__device__ __forceinline__ unsigned long long ffma2(unsigned long long a,
                                                    unsigned long long b,
                                                    unsigned long long c) {
    unsigned long long d;
    asm("fma.rn.f32x2 %0, %1, %2, %3;" : "=l"(d) : "l"(a), "l"(b), "l"(c));
    return d;
}
__device__ __forceinline__ void unpack2(unsigned long long v, float& lo, float& hi) {
    asm("mov.b64 {%0, %1}, %2;" : "=f"(lo), "=f"(hi) : "l"(v));
}
__device__ __forceinline__ float sigf(float v) { return 1.f / (1.f + expf(-v)); }

__device__ __forceinline__ int kpbase(int l) {
    return (l == 1) ? 0 : (l == 2) ? 320 : (l == 3) ? 520 : 648;
}
__device__ __forceinline__ float* cbuf_ptr(int l) {
    const int off = (l == 1) ? 0 : (l == 2) ? 640 : (l == 3) ? 1040 : 1296;
    return g_cbuf + (size_t)off * 128;
}
__device__ __forceinline__ float* xkb_ptr(int par, int l) {
    const int off = (l == 2) ? 0 : (l == 3) ? 1600 : 2624;
    return g_xkbuf[par] + (size_t)off * 128;
}

// fp16 mma: D += A(16x16) * B(16x8), A row-major frag, B col-major frag, f32 acc
__device__ __forceinline__ void mma_f16(float* d,
                                        unsigned a0, unsigned a1, unsigned a2, unsigned a3,
                                        unsigned b0, unsigned b1) {
    asm volatile("mma.sync.aligned.m16n8k16.row.col.f32.f16.f16.f32 "
                 "{%0,%1,%2,%3}, {%4,%5,%6,%7}, {%8,%9}, {%0,%1,%2,%3};"
                 : "+f"(d[0]), "+f"(d[1]), "+f"(d[2]), "+f"(d[3])
                 : "r"(a0), "r"(a1), "r"(a2), "r"(a3), "r"(b0), "r"(b1));
}

// ---- reset state before wavefront ----
__global__ void reset_all() {
    size_t i = (size_t)blockIdx.x * blockDim.x + threadIdx.x;
    const size_t N1 = (size_t)2 * 776 * 128;   // 198656
    if (i < N1) (&g_h2[0][0])[i] = 0u;
    if (i < (size_t)1552 * 128) g_cbuf[i] = 0.f;
    if (i == 0) g_bar = 0u;
}

// ---- layer-1 input-projection GEMM: x[B][T][64] @ k1 -> g_xk [t][4][640][B] fp32 ----
__global__ void gemm_bias_kernel(const float* __restrict__ A, const float* __restrict__ W,
                                 const float* __restrict__ bias, float* __restrict__ C,
                                 int M, int N, int K) {
    __shared__ float As[16][64];
    __shared__ float Ws[16][64];
    const int H = N >> 2;
    int tid = threadIdx.x;
    int n0 = blockIdx.x * 64, m0 = blockIdx.y * 64;
    int tn = tid & 15, tm = tid >> 4;
    int ak = tid & 15, am = tid >> 4;
    int wn = tid & 63, wk = tid >> 6;

    unsigned long long acc01[4], acc23[4];
#pragma unroll
    for (int i = 0; i < 4; i++) { acc01[i] = pack2(0.f, 0.f); acc23[i] = acc01[i]; }

    size_t srow[4];
#pragma unroll
    for (int i = 0; i < 4; i++) {
        int m = m0 + am + i * 16;
        srow[i] = (size_t)(m % BATCH) * SEQT + (size_t)(m / BATCH);
    }

    for (int k0 = 0; k0 < K; k0 += 16) {
#pragma unroll
        for (int i = 0; i < 4; i++)
            As[ak][am + i * 16] = A[srow[i] * K + k0 + ak];
#pragma unroll
        for (int i = 0; i < 4; i++)
            Ws[wk + i * 4][wn] = W[(size_t)(k0 + wk + i * 4) * N + n0 + wn];
        __syncthreads();
#pragma unroll
        for (int k = 0; k < 16; k++) {
            float4 a4 = *(const float4*)&As[k][tm * 4];
            float4 w4 = *(const float4*)&Ws[k][tn * 4];
            unsigned long long a01 = pack2(a4.x, a4.y);
            unsigned long long a23 = pack2(a4.z, a4.w);
            float warr[4] = {w4.x, w4.y, w4.z, w4.w};
#pragma unroll
            for (int j4 = 0; j4 < 4; j4++) {
                unsigned long long wd = pack2(warr[j4], warr[j4]);
                acc01[j4] = ffma2(a01, wd, acc01[j4]);
                acc23[j4] = ffma2(a23, wd, acc23[j4]);
            }
        }
        __syncthreads();
    }
    int t = m0 >> 7;
    int bb = (m0 & 127) + tm * 4;
#pragma unroll
    for (int j4 = 0; j4 < 4; j4++) {
        int n = n0 + tn * 4 + j4;
        int g = n / H;
        int jj = n - g * H;
        float bn = bias[n];
        float v0, v1, v2, v3;
        unpack2(acc01[j4], v0, v1);
        unpack2(acc23[j4], v2, v3);
        *(float4*)&C[((size_t)(t * 4 + g) * H + jj) * 128 + bb] =
            make_float4(v0 + bn, v1 + bn, v2 + bn, v3 + bn);
    }
}

// ---- grid barrier (148 blocks, 1/SM guaranteed by smem); tid0-only fence ----
__device__ __forceinline__ void grid_sync(unsigned int target) {
    __syncthreads();
    if (threadIdx.x == 0) {
        __threadfence();
        atomicAdd(&g_bar, 1u);
        unsigned int v;
        do {
            asm volatile("ld.acquire.gpu.u32 %0, [%1];" : "=r"(v) : "l"(&g_bar));
        } while (v < target);
    }
    __syncthreads();
}

// ---- wavefront persistent loop with fp16 MMA (1 MMA/tile) ----
// 256 threads = 8 warps; warp w owns batch rows 16w..16w+15.
// A (h) staged per k16 chunk as k-pair u32 [8][136], double buffered.
// Weights resident in smem as fp16 plane [n][KPW] k-pair u32.
template<int MAXNT>
__device__ __forceinline__ void persist_loop(
    int isrec, int layer, int Hin, int Hout, int ntiles, int jstart, int toff,
    const float* __restrict__ bias,
    const unsigned int* __restrict__ wsm,
    unsigned int* __restrict__ bufA, float* __restrict__ zbuf, int KPW,
    const float* __restrict__ xk1)
{
    const int tid = threadIdx.x;
    const int lane = tid & 31, w = tid >> 5;
    const int r = lane >> 2, cc = lane & 3;
    const unsigned int nb = gridDim.x;
    const int NKC = Hin >> 4;
    const int srcl = isrec ? layer : layer - 1;
    const int srcKp = kpbase(srcl);
    const int dstKp = kpbase(layer);
    float* cst = cbuf_ptr(layer);
    const int klq = tid >> 5;            // staging row 0..7
    const int bq = (tid & 31) * 4;       // staging col

    for (int s = 0; s < TSTEPS; s++) {
        int t = s - toff;
        if (t >= 0 && t < SEQT) {
            int par = t & 1;
            int spar = isrec ? (par ^ 1) : par;
            const unsigned int* hs = g_h2[spar] + (size_t)srcKp * 128;

            float acc[MAXNT][4];
#pragma unroll
            for (int nt = 0; nt < MAXNT; nt++) {
                acc[nt][0] = 0.f; acc[nt][1] = 0.f; acc[nt][2] = 0.f; acc[nt][3] = 0.f;
            }

            // stage chunk 0
            uint4 pfh = *(const uint4*)(hs + tid * 4);
            *(uint4*)(bufA + klq * 136 + bq) = pfh;
            __syncthreads();
            if (NKC > 1) pfh = *(const uint4*)(hs + 1024 + tid * 4);

            for (int c = 0; c < NKC; c++) {
                const unsigned int* bh = bufA + (c & 1) * 1088;
                unsigned ah0 = bh[cc * 136 + 16 * w + r];
                unsigned ah1 = bh[cc * 136 + 16 * w + r + 8];
                unsigned ah2 = bh[(cc + 4) * 136 + 16 * w + r];
                unsigned ah3 = bh[(cc + 4) * 136 + 16 * w + r + 8];
                int kp0 = c * 8;
#pragma unroll
                for (int nt = 0; nt < MAXNT; nt++) {
                    if (nt < ntiles) {
                        int n = nt * 8 + r;
                        unsigned b0 = wsm[n * KPW + kp0 + cc];
                        unsigned b1 = wsm[n * KPW + kp0 + cc + 4];
                        mma_f16(acc[nt], ah0, ah1, ah2, ah3, b0, b1);
                    }
                }
                if (c + 1 < NKC) {
                    unsigned int* dh = bufA + ((c + 1) & 1) * 1088;
                    *(uint4*)(dh + klq * 136 + bq) = pfh;
                    __syncthreads();
                    if (c + 2 < NKC)
                        pfh = *(const uint4*)(hs + (size_t)(c + 2) * 1024 + tid * 4);
                }
            }

            // D fragments -> zbuf[n][b] (pitch 132)
#pragma unroll
            for (int nt = 0; nt < MAXNT; nt++) {
                if (nt < ntiles) {
                    int nb0 = nt * 8 + 2 * cc;
                    int br = 16 * w + r;
                    zbuf[nb0 * 132 + br] = acc[nt][0];
                    zbuf[(nb0 + 1) * 132 + br] = acc[nt][1];
                    zbuf[nb0 * 132 + br + 8] = acc[nt][2];
                    zbuf[(nb0 + 1) * 132 + br + 8] = acc[nt][3];
                }
            }
            __syncthreads();

            if (isrec) {
                const float* xsrc = (layer == 1) ? (xk1 + (size_t)t * 2560 * 128)
                                                 : xkb_ptr(par, layer);
                unsigned short* hh = (unsigned short*)(g_h2[par] + (size_t)dstKp * 128);
#pragma unroll
                for (int e = 0; e < MAXNT; e++) {
                    if (e < ntiles) {
                        int idx = e * 256 + tid;
                        int jl = idx >> 7, b = idx & 127;
                        int jg = jstart + jl;
                        float zi = zbuf[(jl * 4 + 0) * 132 + b] + xsrc[(size_t)(0 * Hout + jg) * 128 + b];
                        float zf = zbuf[(jl * 4 + 1) * 132 + b] + xsrc[(size_t)(1 * Hout + jg) * 128 + b];
                        float zg = zbuf[(jl * 4 + 2) * 132 + b] + xsrc[(size_t)(2 * Hout + jg) * 128 + b];
                        float zo = zbuf[(jl * 4 + 3) * 132 + b] + xsrc[(size_t)(3 * Hout + jg) * 128 + b];
                        float ig = sigf(zi), fg = sigf(zf);
                        float gg = tanhf(zg), og = sigf(zo);
                        size_t ci = (size_t)jg * 128 + b;
                        float cn = fg * cst[ci] + ig * gg;
                        float h = og * tanhf(cn);
                        cst[ci] = cn;
                        size_t widx = ((size_t)(jg >> 1) * 128 + b) * 2 + (jg & 1);
                        hh[widx] = __half_as_ushort(__float2half_rn(h));
                    }
                }
            } else {
                float* dst = xkb_ptr(par, layer);
#pragma unroll
                for (int e = 0; e < MAXNT; e++) {
                    if (e < ntiles) {
                        int idx = e * 256 + tid;
                        int jl = idx >> 7, b = idx & 127;
                        int jg = jstart + jl;
#pragma unroll
                        for (int g = 0; g < 4; g++)
                            dst[(size_t)(g * Hout + jg) * 128 + b] =
                                zbuf[(jl * 4 + g) * 132 + b] + bias[g * Hout + jg];
                    }
                }
            }
        }
        grid_sync((unsigned int)(s + 1) * nb);
    }
}

__global__ void __launch_bounds__(256, 1)
fused_lstm(const float* __restrict__ R1, const float* __restrict__ K2,
           const float* __restrict__ B2, const float* __restrict__ R2,
           const float* __restrict__ K3, const float* __restrict__ B3,
           const float* __restrict__ R3, const float* __restrict__ K4,
           const float* __restrict__ B4, const float* __restrict__ R4,
           const float* __restrict__ xk1) {
    extern __shared__ unsigned int smem[];

    // roles: 0 L1rec, 1 L2proj, 2 L2rec, 3 L3proj, 4 L3rec, 5 L4proj, 6 L4rec
    const int r_nb[7]    = {54, 34, 21, 13, 9, 9, 8};
    const int r_rec[7]   = {1, 0, 1, 0, 1, 0, 1};
    const int r_layer[7] = {1, 2, 2, 3, 3, 4, 4};
    const int r_Hin[7]   = {640, 640, 400, 400, 256, 256, 256};
    const int r_Hout[7]  = {640, 400, 400, 256, 256, 256, 256};
    const int r_tiles[7] = {320, 200, 200, 128, 128, 128, 128};

    int bid = blockIdx.x;
    int role = 0, start = 0;
    {
        int s2 = 0;
        for (int rr = 0; rr < 7; rr++) {
            if (bid >= s2 && bid < s2 + r_nb[rr]) { role = rr; start = s2; }
            s2 += r_nb[rr];
        }
    }
    int ridx = bid - start;
    const int Hin = r_Hin[role], Hout = r_Hout[role];
    const int layer = r_layer[role], isrec = r_rec[role];
    const int T = r_tiles[role];
    const int q = T / r_nb[role], rm = T % r_nb[role];
    const int ntiles = q + (ridx < rm ? 1 : 0);
    const int tstart = ridx * q + (ridx < rm ? ridx : rm);
    const int jstart = tstart * 2;
    const int kpairs = Hin >> 1;
    const int KPW = (Hin == 640) ? 324 : (Hin == 400) ? 228 : 132;
    const int Nn = ntiles * 8;

    unsigned int* wsm = smem;
    unsigned int* bufA = smem + (size_t)Nn * KPW;
    float* zbuf = (float*)(bufA + 2176);

    const float* Wsel = (role == 0) ? R1 : (role == 1) ? K2 : (role == 2) ? R2
                       : (role == 3) ? K3 : (role == 4) ? R3 : (role == 5) ? K4 : R4;
    const float* bias = (role == 1) ? B2 : (role == 3) ? B3 : (role == 5) ? B4 : (const float*)0;

    // preamble: load fp32 weights, convert to fp16 k-pair u32 layout [n][KPW]
    {
        int tid = threadIdx.x;
        int tot = Nn * kpairs;
        for (int e = tid; e < tot; e += 256) {
            int n = e / kpairs, kp = e - n * kpairs;
            int jl = n >> 2, g = n & 3;
            int gcol = g * Hout + jstart + jl;
            float w0 = Wsel[(size_t)(2 * kp) * (4 * Hout) + gcol];
            float w1 = Wsel[(size_t)(2 * kp + 1) * (4 * Hout) + gcol];
            unsigned u0 = (unsigned)__half_as_ushort(__float2half_rn(w0));
            unsigned u1 = (unsigned)__half_as_ushort(__float2half_rn(w1));
            wsm[n * KPW + kp] = u0 | (u1 << 16);
        }
    }
    __syncthreads();

    if (role <= 1)
        persist_loop<6>(isrec, layer, Hin, Hout, ntiles, jstart, role, bias,
                        wsm, bufA, zbuf, KPW, xk1);
    else if (role <= 3)
        persist_loop<10>(isrec, layer, Hin, Hout, ntiles, jstart, role, bias,
                         wsm, bufA, zbuf, KPW, xk1);
    else
        persist_loop<16>(isrec, layer, Hin, Hout, ntiles, jstart, role, bias,
                         wsm, bufA, zbuf, KPW, xk1);
}

// ---- dense head: 6 FC layers + softmax; h4 fp16 (par 1) ----
__device__ __forceinline__ void dense_layer(const float* __restrict__ W,
                                            const float* __restrict__ bi,
                                            const float* in, float* out2,
                                            int din, int dout, bool relu) {
    for (int j = threadIdx.x; j < dout; j += blockDim.x) {
        float s = bi[j];
        for (int kk = 0; kk < din; kk++) s += in[kk] * W[(size_t)kk * dout + j];
        out2[j] = relu ? fmaxf(s, 0.f) : s;
    }
    __syncthreads();
}

__global__ void dense_head_kernel(const float* w1, const float* b1,
                                  const float* w2, const float* b2,
                                  const float* w3, const float* b3,
                                  const float* w4, const float* b4,
                                  const float* w5, const float* b5,
                                  const float* w6, const float* b6,
                                  float* __restrict__ out) {
    __shared__ float bufa[512], bufb[512];
    int b = blockIdx.x;
    const unsigned short* hh = (const unsigned short*)(g_h2[1] + (size_t)648 * 128);
    for (int j = threadIdx.x; j < 256; j += blockDim.x) {
        size_t widx = ((size_t)(j >> 1) * 128 + b) * 2 + (j & 1);
        bufa[j] = __half2float(__ushort_as_half(hh[widx]));
    }
    __syncthreads();
    dense_layer(w1, b1, bufa, bufb, 256, 512, true);
    dense_layer(w2, b2, bufb, bufa, 512, 256, true);
    dense_layer(w3, b3, bufa, bufb, 256, 128, true);
    dense_layer(w4, b4, bufb, bufa, 128, 64, true);
    dense_layer(w5, b5, bufa, bufb, 64, 16, true);
    dense_layer(w6, b6, bufb, bufa, 16, 3, false);
    if (threadIdx.x == 0) {
        float m = fmaxf(bufa[0], fmaxf(bufa[1], bufa[2]));
        float e0 = expf(bufa[0] - m), e1 = expf(bufa[1] - m), e2 = expf(bufa[2] - m);
        float s = e0 + e1 + e2;
        out[b * 3 + 0] = e0 / s;
        out[b * 3 + 1] = e1 / s;
        out[b * 3 + 2] = e2 / s;
    }
}

extern "C" void kernel_launch(void* const* d_in, const int* in_sizes, int n_in,
                              void* d_out, int out_size) {
    const float* x  = (const float*)d_in[0];
    const float* k1 = (const float*)d_in[1];
    const float* r1 = (const float*)d_in[2];
    const float* b1 = (const float*)d_in[3];
    const float* k2 = (const float*)d_in[4];
    const float* r2 = (const float*)d_in[5];
    const float* b2 = (const float*)d_in[6];
    const float* k3 = (const float*)d_in[7];
    const float* r3 = (const float*)d_in[8];
    const float* b3 = (const float*)d_in[9];
    const float* k4 = (const float*)d_in[10];
    const float* r4 = (const float*)d_in[11];
    const float* b4 = (const float*)d_in[12];
    const float* WD[6];
    const float* BD[6];
    for (int i = 0; i < 6; i++) {
        WD[i] = (const float*)d_in[13 + 2 * i];
        BD[i] = (const float*)d_in[14 + 2 * i];
    }

    float* xk;
    cudaGetSymbolAddress((void**)&xk, g_xk);

    // max smem over roles: role6 = (128*132 + 2176)*4 + 128*132*4 = 143872 B
    const int SMEMB = 147456;
    cudaFuncSetAttribute(fused_lstm, cudaFuncAttributeMaxDynamicSharedMemorySize, SMEMB);

    const int M = BATCH * SEQT;

    // 1) layer-1 input projection GEMM (fp32)
    gemm_bias_kernel<<<dim3(2560 / 64, M / 64), 256>>>(x, k1, b1, xk, M, 2560, 64);
    // 2) zero h/c/barrier
    reset_all<<<776, 256>>>();
    // 3) fused 4-layer wavefront, fp16 tensor-core matmuls (1 MMA/tile)
    fused_lstm<<<NBLK, 256, SMEMB>>>(r1, k2, b2, r2, k3, b3, r3, k4, b4, r4, xk);
    // 4) dense head + softmax
    dense_head_kernel<<<BATCH, 256>>>(WD[0], BD[0], WD[1], BD[1], WD[2], BD[2],
                                      WD[3], BD[3], WD[4], BD[4], WD[5], BD[5],
                                      (float*)d_out);
}